// round 9
// baseline (speedup 1.0000x reference)
#include <cuda_runtime.h>
#include <cuda_bf16.h>
#include <cstdint>

// ---------------------------------------------------------------------------
// VQ-VAE VectorQuantizer3 forward.
// R9 = R8 resubmit (R8 hit a broker/container infra failure, never executed).
// Distance kernel re-tiled to 128 rows x 1024 codes per CTA (4x fewer CTAs --
// tests/exploits the measured fixed per-CTA cost), B streamed in 8
// double-buffered chunks. Patchify fused into GEMM1 A-loads, unpatchify fused
// into GEMM2 C-stores, loss folded into the candidate rescore.
// idx is bit-identical to the R2 exact fp32 semantics via candidate rescore.
// Out: out(8388608) | loss(1) | idx(8192)   (float32)
// ---------------------------------------------------------------------------

#define NROWS 8192
#define EDIM  256
#define NCODE 16384
#define PIN   1024
#define OUT_ELEMS 8388608
#define TKP 18
#define CAND_MARGIN 1e-3f

// k_mma_dist smem layout
#define BOFF   67584                  // A: 128 rows * 528B
#define SENOFF 202752                 // B: 2 * 67584
#define MDOFF  206848
#define MJOFF  215040
#define DSMEM2 223232

typedef unsigned long long ull;

// ------------------------------ scratch -------------------------------------
__device__ float g_x[NROWS * EDIM];
__device__ float g_zf[NROWS * EDIM];
__device__ float g_rn[NROWS];
__device__ float g_wpet[EDIM * PIN];
__device__ float g_wput[PIN * EDIM];
__device__ float g_en[NCODE];
__device__ __nv_bfloat16 g_zbf[NROWS * EDIM];   // bf16(zf)
__device__ __nv_bfloat16 g_ebf[NCODE * EDIM];   // bf16(emb)
__device__ float g_cd[NROWS * 512];             // top-4 per (row, 128-code tile)
__device__ int   g_cj[NROWS * 512];
__device__ int   g_idx[NROWS];
__device__ float g_lossr[NROWS];

// ------------------------------ fp32x2 helpers -------------------------------
__device__ __forceinline__ ull fma2(ull a, ull b, ull c) {
    ull d;
    asm("fma.rn.f32x2 %0, %1, %2, %3;" : "=l"(d) : "l"(a), "l"(b), "l"(c));
    return d;
}
__device__ __forceinline__ void unpack2(ull v, float& lo, float& hi) {
    asm("mov.b64 {%0, %1}, %2;" : "=f"(lo), "=f"(hi) : "l"(v));
}
__device__ __forceinline__ void st4(float* p, float4 v) {
    p[0] = v.x; p[1] = v.y; p[2] = v.z; p[3] = v.w;
}
__device__ __forceinline__ ull lds2(const float* p) {
    return *reinterpret_cast<const ull*>(p);
}

// ------------------------------ mma helpers ----------------------------------
__device__ __forceinline__ uint32_t smem_u32(const void* p) {
    uint32_t a;
    asm("{ .reg .u64 t; cvta.to.shared.u64 t, %1; cvt.u32.u64 %0, t; }"
        : "=r"(a) : "l"(p));
    return a;
}
__device__ __forceinline__ void cpa16(uint32_t dst, const void* src) {
    asm volatile("cp.async.ca.shared.global [%0], [%1], 16;"
                 :: "r"(dst), "l"(src) : "memory");
}
__device__ __forceinline__ void cpa8(uint32_t dst, const void* src) {
    asm volatile("cp.async.ca.shared.global [%0], [%1], 8;"
                 :: "r"(dst), "l"(src) : "memory");
}
#define CP_COMMIT() asm volatile("cp.async.commit_group;" ::: "memory")
#define CP_WAIT1()  asm volatile("cp.async.wait_group 1;" ::: "memory")
#define CP_WAIT0()  asm volatile("cp.async.wait_group 0;" ::: "memory")

__device__ __forceinline__ void ldm4(uint32_t& r0, uint32_t& r1,
                                     uint32_t& r2, uint32_t& r3, uint32_t a) {
    asm volatile("ldmatrix.sync.aligned.m8n8.x4.shared.b16 {%0,%1,%2,%3}, [%4];"
                 : "=r"(r0), "=r"(r1), "=r"(r2), "=r"(r3) : "r"(a));
}
__device__ __forceinline__ void mma_bf16(float* c, uint32_t a0, uint32_t a1,
                                         uint32_t a2, uint32_t a3,
                                         uint32_t b0, uint32_t b1) {
    asm volatile(
        "mma.sync.aligned.m16n8k16.row.col.f32.bf16.bf16.f32 "
        "{%0,%1,%2,%3}, {%4,%5,%6,%7}, {%8,%9}, {%0,%1,%2,%3};"
        : "+f"(c[0]), "+f"(c[1]), "+f"(c[2]), "+f"(c[3])
        : "r"(a0), "r"(a1), "r"(a2), "r"(a3), "r"(b0), "r"(b1));
}

// ---------------------------------------------------------------------------
// k_pre1 (launch 1): weight transposes + emb bf16 + norms
// blocks [0,2048): transposes; [2048,4096): emb rows (8 per block)
// ---------------------------------------------------------------------------
__global__ void k_pre1(const float* __restrict__ W_pe,
                       const float* __restrict__ W_pu,
                       const float* __restrict__ emb,
                       float* __restrict__ wpet, float* __restrict__ wput,
                       __nv_bfloat16* __restrict__ ebf, float* __restrict__ en) {
    int b = blockIdx.x, t = threadIdx.x;
    if (b < 2048) {
        int gid = b * 256 + t;
        if (gid < 262144) {            // wpet[e,kin] = W_pe[kin,e]
            int n = gid >> 10, k = gid & 1023;
            wpet[gid] = W_pe[k * 256 + n];
        } else {                       // wput[p,e] = W_pu[e,p]
            int g2 = gid - 262144;
            int n = g2 >> 8, k = g2 & 255;
            wput[g2] = W_pu[k * 1024 + n];
        }
    } else {
        int w = t >> 5, lane = t & 31;
        int j = (b - 2048) * 8 + w;
        const float4* e4 = reinterpret_cast<const float4*>(emb + (size_t)j * EDIM);
        float4 a = e4[lane * 2], c = e4[lane * 2 + 1];
        uint4 bfp;
        __nv_bfloat162 p0 = __float22bfloat162_rn(make_float2(a.x, a.y));
        __nv_bfloat162 p1 = __float22bfloat162_rn(make_float2(a.z, a.w));
        __nv_bfloat162 p2 = __float22bfloat162_rn(make_float2(c.x, c.y));
        __nv_bfloat162 p3 = __float22bfloat162_rn(make_float2(c.z, c.w));
        bfp.x = *reinterpret_cast<uint32_t*>(&p0);
        bfp.y = *reinterpret_cast<uint32_t*>(&p1);
        bfp.z = *reinterpret_cast<uint32_t*>(&p2);
        bfp.w = *reinterpret_cast<uint32_t*>(&p3);
        *reinterpret_cast<uint4*>(ebf + (size_t)j * EDIM + lane * 8) = bfp;
        float s = a.x*a.x + a.y*a.y + a.z*a.z + a.w*a.w
                + c.x*c.x + c.y*c.y + c.z*c.z + c.w*c.w;
        #pragma unroll
        for (int o = 16; o > 0; o >>= 1) s += __shfl_xor_sync(0xffffffffu, s, o);
        if (lane == 0) en[j] = s;
    }
}

// ---------------------------------------------------------------------------
// fp32 NT GEMM. APATCH: A gathered from z with fused patchify.
// GATHER: A row r = A[gidx[r]]. CUNPATCH: C scattered to NCHW layout.
// ---------------------------------------------------------------------------
template<bool APATCH, bool GATHER, bool CUNPATCH>
__global__ void __launch_bounds__(256, 1)
k_gemm(const float* __restrict__ A, const float* __restrict__ B,
       const float* __restrict__ bias, float* __restrict__ C,
       const int* __restrict__ gidx, int K, int N, int kchunks) {
    __shared__ float sA[2][128 * TKP];
    __shared__ float sB[2][128 * TKP];
    int t = threadIdx.x;
    int tx = t & 15, ty = t >> 4;
    int rb = blockIdx.x * 128, cb = blockIdx.y * 128;

    int lr0 = t >> 2, q = t & 3;
    int sb0 = lr0 * TKP + q * 4;
    int sb1 = (64 + lr0) * TKP + q * 4;

    long zb0, zb1;
    if (APATCH) {
        int n0 = rb + lr0, n1 = rb + 64 + lr0;
        zb0 = (long)(n0 >> 10) * 1048576 + ((n0 >> 5) & 31) * 128 + (n0 & 31) * 2;
        zb1 = (long)(n1 >> 10) * 1048576 + ((n1 >> 5) & 31) * 128 + (n1 & 31) * 2;
    } else {
        long ar0 = GATHER ? (long)gidx[rb + lr0]      : (long)(rb + lr0);
        long ar1 = GATHER ? (long)gidx[rb + 64 + lr0] : (long)(rb + 64 + lr0);
        zb0 = ar0 * K + q * 4;
        zb1 = ar1 * K + q * 4;
    }
    const float* bp0 = B + (long)(cb + lr0) * K + q * 4;
    const float* bp1 = B + (long)(cb + 64 + lr0) * K + q * 4;

    #define LOADA(zb, kc) (APATCH ? ({ \
        const float* _p = A + (zb) + (q + (kc) * 4) * 4096; \
        float2 _u = *reinterpret_cast<const float2*>(_p); \
        float2 _v = *reinterpret_cast<const float2*>(_p + 64); \
        make_float4(_u.x, _u.y, _v.x, _v.y); }) \
        : *reinterpret_cast<const float4*>(A + (zb) + (kc) * 16))

    ull acc[8][8];
    #pragma unroll
    for (int i = 0; i < 8; ++i)
        #pragma unroll
        for (int j = 0; j < 8; ++j) acc[i][j] = 0ull;

    float4 ra0 = LOADA(zb0, 0), ra1 = LOADA(zb1, 0);
    float4 rb0 = *reinterpret_cast<const float4*>(bp0);
    float4 rb1 = *reinterpret_cast<const float4*>(bp1);
    st4(&sA[0][sb0], ra0); st4(&sA[0][sb1], ra1);
    st4(&sB[0][sb0], rb0); st4(&sB[0][sb1], rb1);
    __syncthreads();

    for (int kc = 0; kc < kchunks; ++kc) {
        if (kc + 1 < kchunks) {
            int off = (kc + 1) * 16;
            ra0 = LOADA(zb0, kc + 1); ra1 = LOADA(zb1, kc + 1);
            rb0 = *reinterpret_cast<const float4*>(bp0 + off);
            rb1 = *reinterpret_cast<const float4*>(bp1 + off);
        }
        const float* As = sA[kc & 1];
        const float* Bs = sB[kc & 1];
        #pragma unroll
        for (int kp = 0; kp < 8; ++kp) {
            ull a2[8], b2[8];
            #pragma unroll
            for (int i = 0; i < 8; ++i) a2[i] = lds2(As + (ty + 16 * i) * TKP + kp * 2);
            #pragma unroll
            for (int j = 0; j < 8; ++j) b2[j] = lds2(Bs + (tx + 16 * j) * TKP + kp * 2);
            #pragma unroll
            for (int i = 0; i < 8; ++i)
                #pragma unroll
                for (int j = 0; j < 8; ++j) acc[i][j] = fma2(a2[i], b2[j], acc[i][j]);
        }
        if (kc + 1 < kchunks) {
            int nb = (kc + 1) & 1;
            st4(&sA[nb][sb0], ra0); st4(&sA[nb][sb1], ra1);
            st4(&sB[nb][sb0], rb0); st4(&sB[nb][sb1], rb1);
            __syncthreads();
        }
    }
    #undef LOADA

    float breg[8];
    #pragma unroll
    for (int j = 0; j < 8; ++j) breg[j] = bias[cb + tx + 16 * j];
    #pragma unroll
    for (int i = 0; i < 8; ++i) {
        int n = rb + ty + 16 * i;
        long ob = CUNPATCH
                ? ((long)(n >> 10) * 1048576 + ((n >> 5) & 31) * 128 + (n & 31) * 2)
                : ((long)n * N + cb);
        #pragma unroll
        for (int j = 0; j < 8; ++j) {
            float lo, hi; unpack2(acc[i][j], lo, hi);
            float v = lo + hi + breg[j];
            if (CUNPATCH) {
                int p = cb + tx + 16 * j;
                C[ob + (p >> 2) * 4096 + ((p >> 1) & 1) * 64 + (p & 1)] = v;
            } else {
                C[ob + tx + 16 * j] = v;
            }
        }
    }
}

// ---------------------------------------------------------------------------
// LayerNorm (launch 3) -> zf, rn = ||zf||^2, zbf = bf16(zf)
// ---------------------------------------------------------------------------
__global__ void k_ln(const float* __restrict__ x, const float* __restrict__ gamma,
                     const float* __restrict__ beta, float* __restrict__ zf,
                     float* __restrict__ rn, __nv_bfloat16* __restrict__ zbf) {
    int w = threadIdx.x >> 5, lane = threadIdx.x & 31;
    int row = blockIdx.x * 8 + w;
    const float4* xr = reinterpret_cast<const float4*>(x + (size_t)row * EDIM);
    float4 v0 = xr[lane * 2], v1 = xr[lane * 2 + 1];
    float s = v0.x+v0.y+v0.z+v0.w + v1.x+v1.y+v1.z+v1.w;
    #pragma unroll
    for (int o = 16; o > 0; o >>= 1) s += __shfl_xor_sync(0xffffffffu, s, o);
    float mu = s * (1.0f / 256.0f);
    float d0x=v0.x-mu, d0y=v0.y-mu, d0z=v0.z-mu, d0w=v0.w-mu;
    float d1x=v1.x-mu, d1y=v1.y-mu, d1z=v1.z-mu, d1w=v1.w-mu;
    float s2 = d0x*d0x+d0y*d0y+d0z*d0z+d0w*d0w + d1x*d1x+d1y*d1y+d1z*d1z+d1w*d1w;
    #pragma unroll
    for (int o = 16; o > 0; o >>= 1) s2 += __shfl_xor_sync(0xffffffffu, s2, o);
    float rs = rsqrtf(s2 * (1.0f / 256.0f) + 1e-5f);
    const float4* g4 = reinterpret_cast<const float4*>(gamma);
    const float4* b4 = reinterpret_cast<const float4*>(beta);
    float4 ga = g4[lane * 2], gb = g4[lane * 2 + 1];
    float4 ba = b4[lane * 2], bb = b4[lane * 2 + 1];
    float4 o0, o1;
    o0.x = d0x*rs*ga.x + ba.x; o0.y = d0y*rs*ga.y + ba.y;
    o0.z = d0z*rs*ga.z + ba.z; o0.w = d0w*rs*ga.w + ba.w;
    o1.x = d1x*rs*gb.x + bb.x; o1.y = d1y*rs*gb.y + bb.y;
    o1.z = d1z*rs*gb.z + bb.z; o1.w = d1w*rs*gb.w + bb.w;
    float4* zr = reinterpret_cast<float4*>(zf + (size_t)row * EDIM);
    zr[lane * 2] = o0; zr[lane * 2 + 1] = o1;
    uint4 bfp;
    __nv_bfloat162 p0 = __float22bfloat162_rn(make_float2(o0.x, o0.y));
    __nv_bfloat162 p1 = __float22bfloat162_rn(make_float2(o0.z, o0.w));
    __nv_bfloat162 p2 = __float22bfloat162_rn(make_float2(o1.x, o1.y));
    __nv_bfloat162 p3 = __float22bfloat162_rn(make_float2(o1.z, o1.w));
    bfp.x = *reinterpret_cast<uint32_t*>(&p0);
    bfp.y = *reinterpret_cast<uint32_t*>(&p1);
    bfp.z = *reinterpret_cast<uint32_t*>(&p2);
    bfp.w = *reinterpret_cast<uint32_t*>(&p3);
    *reinterpret_cast<uint4*>(zbf + (size_t)row * EDIM + lane * 8) = bfp;
    float q2 = o0.x*o0.x+o0.y*o0.y+o0.z*o0.z+o0.w*o0.w
             + o1.x*o1.x+o1.y*o1.y+o1.z*o1.z+o1.w*o1.w;
    #pragma unroll
    for (int o = 16; o > 0; o >>= 1) q2 += __shfl_xor_sync(0xffffffffu, q2, o);
    if (lane == 0) rn[row] = q2;
}

// ---------------------------------------------------------------------------
// mma.sync distance kernel (launch 4). CTA: 128 rows x 1024 codes, K=256.
// grid (64, 16), 512 threads = 16 warps (4 row x 4 col), warp tile 32x32.
// A resident; B streamed in 8 chunks of 128 codes, double-buffered cp.async.
// Per-chunk epilogue: top-4 smallest d = en[j] - 2*dot per (row, 128-tile).
// ---------------------------------------------------------------------------
__global__ void __launch_bounds__(512, 1)
k_mma_dist(const __nv_bfloat16* __restrict__ zbf,
           const __nv_bfloat16* __restrict__ ebf,
           const float* __restrict__ en,
           float* __restrict__ cd, int* __restrict__ cj) {
    extern __shared__ char smem[];
    uint32_t sb = smem_u32(smem);
    int t = threadIdx.x, lane = t & 31, w = t >> 5;
    int wr = w >> 2, wc = w & 3;
    int g = lane >> 2, tid4 = lane & 3;
    int rb = blockIdx.x * 128;
    int jb2 = blockIdx.y * 1024;

    int ar = t >> 2, aq = t & 3;
    // prologue group 0: A + sen + B chunk0
    {
        const char* ga = (const char*)(zbf + (size_t)(rb + ar) * EDIM) + aq * 128;
        uint32_t da = sb + (uint32_t)ar * 528 + aq * 128;
        #pragma unroll
        for (int c2 = 0; c2 < 8; ++c2) cpa16(da + c2 * 16, ga + c2 * 16);
        cpa8(sb + SENOFF + (uint32_t)t * 8, en + jb2 + t * 2);
        const char* gb = (const char*)(ebf + (size_t)(jb2 + ar) * EDIM) + aq * 128;
        uint32_t db = sb + BOFF + (uint32_t)ar * 528 + aq * 128;
        #pragma unroll
        for (int c2 = 0; c2 < 8; ++c2) cpa16(db + c2 * 16, gb + c2 * 16);
    }
    CP_COMMIT();
    // prologue group 1: B chunk1
    {
        const char* gb = (const char*)(ebf + (size_t)(jb2 + 128 + ar) * EDIM) + aq * 128;
        uint32_t db = sb + BOFF + 67584 + (uint32_t)ar * 528 + aq * 128;
        #pragma unroll
        for (int c2 = 0; c2 < 8; ++c2) cpa16(db + c2 * 16, gb + c2 * 16);
    }
    CP_COMMIT();

    uint32_t ab = sb + (uint32_t)(wr * 32 + (lane & 15)) * 528 + (lane >> 4) * 16;
    const float* sen = reinterpret_cast<const float*>(smem + SENOFF);
    float* md = reinterpret_cast<float*>(smem + MDOFF);
    int*   mj = reinterpret_cast<int*>(smem + MJOFF);

    for (int ck = 0; ck < 8; ++ck) {
        if (ck < 7) CP_WAIT1(); else CP_WAIT0();
        __syncthreads();
        int buf = ck & 1;
        uint32_t bb = sb + BOFF + (uint32_t)buf * 67584
                    + (uint32_t)(wc * 32 + (lane & 7) + ((lane >> 4) & 1) * 8) * 528
                    + ((lane >> 3) & 1) * 16;

        float c[2][4][4];
        #pragma unroll
        for (int mi = 0; mi < 2; ++mi)
            #pragma unroll
            for (int ni = 0; ni < 4; ++ni)
                #pragma unroll
                for (int s = 0; s < 4; ++s) c[mi][ni][s] = 0.0f;

        #pragma unroll
        for (int ks = 0; ks < 16; ++ks) {
            uint32_t ko = (uint32_t)ks * 32;
            uint32_t A0[2], A1[2], A2[2], A3[2];
            #pragma unroll
            for (int mi = 0; mi < 2; ++mi)
                ldm4(A0[mi], A1[mi], A2[mi], A3[mi], ab + mi * 8448 + ko);
            uint32_t B0[2], B1[2], B2[2], B3[2];
            #pragma unroll
            for (int np = 0; np < 2; ++np)
                ldm4(B0[np], B1[np], B2[np], B3[np], bb + np * 8448 + ko);
            #pragma unroll
            for (int mi = 0; mi < 2; ++mi)
                #pragma unroll
                for (int ni = 0; ni < 4; ++ni) {
                    int np = ni >> 1;
                    if (ni & 1)
                        mma_bf16(c[mi][ni], A0[mi], A1[mi], A2[mi], A3[mi],
                                 B2[np], B3[np]);
                    else
                        mma_bf16(c[mi][ni], A0[mi], A1[mi], A2[mi], A3[mi],
                                 B0[np], B1[np]);
                }
        }

        // per-chunk epilogue: top-4 per (row, this 128-code tile)
        float enr[4][2];
        #pragma unroll
        for (int ni = 0; ni < 4; ++ni) {
            int cl = ck * 128 + wc * 32 + ni * 8 + tid4 * 2;
            enr[ni][0] = sen[cl];
            enr[ni][1] = sen[cl + 1];
        }
        #pragma unroll
        for (int mi = 0; mi < 2; ++mi) {
            #pragma unroll
            for (int sh = 0; sh < 2; ++sh) {
                int row = wr * 32 + mi * 16 + g + 8 * sh;
                float bv[4] = {3.4e38f, 3.4e38f, 3.4e38f, 3.4e38f};
                int bj4[4] = {0, 0, 0, 0};
                float wmax = 3.4e38f; int wpos = 0;
                #pragma unroll
                for (int ni = 0; ni < 4; ++ni)
                    #pragma unroll
                    for (int p = 0; p < 2; ++p) {
                        float d = __fmaf_rn(-2.0f, c[mi][ni][sh * 2 + p], enr[ni][p]);
                        if (d < wmax) {
                            bv[wpos] = d;
                            bj4[wpos] = jb2 + ck * 128 + wc * 32 + ni * 8 + tid4 * 2 + p;
                            wmax = bv[0]; wpos = 0;
                            #pragma unroll
                            for (int s = 1; s < 4; ++s)
                                if (bv[s] > wmax) { wmax = bv[s]; wpos = s; }
                        }
                    }
                #pragma unroll
                for (int off = 1; off <= 2; off <<= 1) {
                    #pragma unroll
                    for (int s = 0; s < 4; ++s) {
                        float od = __shfl_xor_sync(0xffffffffu, bv[s], off);
                        int   oj = __shfl_xor_sync(0xffffffffu, bj4[s], off);
                        if (od < wmax) {
                            bv[wpos] = od; bj4[wpos] = oj;
                            wmax = bv[0]; wpos = 0;
                            #pragma unroll
                            for (int qq = 1; qq < 4; ++qq)
                                if (bv[qq] > wmax) { wmax = bv[qq]; wpos = qq; }
                        }
                    }
                }
                if (tid4 == 0) {
                    #pragma unroll
                    for (int s = 0; s < 4; ++s) {
                        md[row * 16 + wc * 4 + s] = bv[s];
                        mj[row * 16 + wc * 4 + s] = bj4[s];
                    }
                }
            }
        }
        __syncthreads();
        if (t < 128) {
            float bv[4]; int bj4[4];
            #pragma unroll
            for (int s = 0; s < 4; ++s) { bv[s] = md[t * 16 + s]; bj4[s] = mj[t * 16 + s]; }
            float wmax = bv[0]; int wpos = 0;
            #pragma unroll
            for (int s = 1; s < 4; ++s) if (bv[s] > wmax) { wmax = bv[s]; wpos = s; }
            #pragma unroll
            for (int u = 4; u < 16; ++u) {
                float od = md[t * 16 + u]; int oj = mj[t * 16 + u];
                if (od < wmax) {
                    bv[wpos] = od; bj4[wpos] = oj;
                    wmax = bv[0]; wpos = 0;
                    #pragma unroll
                    for (int qq = 1; qq < 4; ++qq)
                        if (bv[qq] > wmax) { wmax = bv[qq]; wpos = qq; }
                }
            }
            size_t base = (size_t)(rb + t) * 512 + (size_t)(blockIdx.y * 8 + ck) * 4;
            #pragma unroll
            for (int s = 0; s < 4; ++s) { cd[base + s] = bv[s]; cj[base + s] = bj4[s]; }
        }
        // prefetch chunk ck+2 into the buffer we just finished reading
        if (ck + 2 < 8) {
            const char* gb = (const char*)(ebf
                           + (size_t)(jb2 + (ck + 2) * 128 + ar) * EDIM) + aq * 128;
            uint32_t db = sb + BOFF + (uint32_t)buf * 67584
                        + (uint32_t)ar * 528 + aq * 128;
            #pragma unroll
            for (int c2 = 0; c2 < 8; ++c2) cpa16(db + c2 * 16, gb + c2 * 16);
            CP_COMMIT();
        }
    }
}

// ---------------------------------------------------------------------------
// candidate merge + exact fp32 rescore (launch 5; R2-identical semantics).
// 512 entries per row (top-4 x 128 tiles). Also emits per-row loss term.
// ---------------------------------------------------------------------------
__global__ void __launch_bounds__(256)
k_cand(const float* __restrict__ cd, const int* __restrict__ cj,
       const float* __restrict__ zf, const float* __restrict__ emb,
       const float* __restrict__ en, const float* __restrict__ rn,
       int* __restrict__ idxo, float* __restrict__ fout,
       float* __restrict__ lossr) {
    __shared__ int lst[8][512];
    __shared__ int cnt[8];
    int w = threadIdx.x >> 5, lane = threadIdx.x & 31;
    int row = blockIdx.x * 8 + w;
    if (lane == 0) cnt[w] = 0;
    __syncwarp();

    float dv[16]; int jv[16];
    size_t base = (size_t)row * 512 + lane * 16;
    #pragma unroll
    for (int s = 0; s < 16; ++s) { dv[s] = cd[base + s]; jv[s] = cj[base + s]; }
    float mn = dv[0];
    #pragma unroll
    for (int s = 1; s < 16; ++s) mn = fminf(mn, dv[s]);
    #pragma unroll
    for (int o = 16; o > 0; o >>= 1)
        mn = fminf(mn, __shfl_xor_sync(0xffffffffu, mn, o));
    float thr = mn + CAND_MARGIN;
    #pragma unroll
    for (int s = 0; s < 16; ++s) {
        if (dv[s] <= thr) {
            int pos = atomicAdd(&cnt[w], 1);
            lst[w][pos] = jv[s];
        }
    }
    __syncwarp();
    int m = cnt[w];

    float bd = 3.4e38f; int bj = 0x7fffffff;
    const float2* z2 = reinterpret_cast<const float2*>(zf + (size_t)row * EDIM);
    float rnv = rn[row];
    for (int cc = lane; cc < m; cc += 32) {
        int j = lst[w][cc];
        const float2* e2 = reinterpret_cast<const float2*>(emb + (size_t)j * EDIM);
        float lo = 0.0f, hi = 0.0f;
        #pragma unroll 8
        for (int qq = 0; qq < 128; ++qq) {
            float2 zz = z2[qq], ee = e2[qq];
            lo = __fmaf_rn(zz.x, ee.x, lo);
            hi = __fmaf_rn(zz.y, ee.y, hi);
        }
        float dot = __fadd_rn(lo, hi);
        float t1  = __fadd_rn(rnv, en[j]);
        float d   = __fsub_rn(t1, __fmul_rn(2.0f, dot));
        if (d < bd || (d == bd && j < bj)) { bd = d; bj = j; }
    }
    #pragma unroll
    for (int o = 16; o > 0; o >>= 1) {
        float od = __shfl_xor_sync(0xffffffffu, bd, o);
        int   oj = __shfl_xor_sync(0xffffffffu, bj, o);
        if (od < bd || (od == bd && oj < bj)) { bd = od; bj = oj; }
    }
    if (lane == 0) {
        idxo[row] = bj;
        fout[OUT_ELEMS + 1 + row] = (float)bj;
        lossr[row] = bd;                 // = ||e_bj - zf_row||^2 (R2 rounding)
    }
}

// ---------------------------------------------------------------------------
__global__ void k_fin2(const float* __restrict__ lossr, float* __restrict__ out) {
    __shared__ float sm[256];
    int t = threadIdx.x;
    float s = 0.0f;
    for (int i = t; i < NROWS; i += 256) s += lossr[i];
    sm[t] = s;
    __syncthreads();
    #pragma unroll
    for (int o = 128; o > 0; o >>= 1) {
        if (t < o) sm[t] += sm[t + o];
        __syncthreads();
    }
    if (t == 0) out[OUT_ELEMS] = 1.25f * sm[0] / 2097152.0f;
}

// ---------------------------------------------------------------------------
extern "C" void kernel_launch(void* const* d_in, const int* in_sizes, int n_in,
                              void* d_out, int out_size) {
    const float* z     = (const float*)d_in[0];
    const float* emb   = (const float*)d_in[1];
    const float* W_pe  = (const float*)d_in[2];
    const float* b_pe  = (const float*)d_in[3];
    const float* gamma = (const float*)d_in[4];
    const float* beta  = (const float*)d_in[5];
    const float* W_pu  = (const float*)d_in[6];
    const float* b_pu  = (const float*)d_in[7];
    float* out = (float*)d_out;

    float *x, *zf, *rn, *wpet, *wput, *en, *cdp, *lossr;
    __nv_bfloat16 *zbf, *ebf;
    int *cjp, *idx;
    cudaGetSymbolAddress((void**)&x,     g_x);
    cudaGetSymbolAddress((void**)&zf,    g_zf);
    cudaGetSymbolAddress((void**)&rn,    g_rn);
    cudaGetSymbolAddress((void**)&wpet,  g_wpet);
    cudaGetSymbolAddress((void**)&wput,  g_wput);
    cudaGetSymbolAddress((void**)&en,    g_en);
    cudaGetSymbolAddress((void**)&zbf,   g_zbf);
    cudaGetSymbolAddress((void**)&ebf,   g_ebf);
    cudaGetSymbolAddress((void**)&cdp,   g_cd);
    cudaGetSymbolAddress((void**)&cjp,   g_cj);
    cudaGetSymbolAddress((void**)&idx,   g_idx);
    cudaGetSymbolAddress((void**)&lossr, g_lossr);

    cudaFuncSetAttribute(k_mma_dist, cudaFuncAttributeMaxDynamicSharedMemorySize,
                         DSMEM2);

    // 1: prep (transposes + emb bf16/norms)
    k_pre1<<<4096, 256>>>(W_pe, W_pu, emb, wpet, wput, ebf, en);
    // 2: x = patchify(z) @ W_pe + b_pe   (patchify fused into A-loads)
    k_gemm<true, false, false><<<dim3(64, 2), 256>>>(z, wpet, b_pe, x, nullptr,
                                                     PIN, EDIM, PIN / 16);
    // 3: LayerNorm (+ rn, zbf)
    k_ln<<<NROWS / 8, 256>>>(x, gamma, beta, zf, rn, zbf);
    // 4: tensor-core distance, 128x1024 per CTA (profiled slot)
    k_mma_dist<<<dim3(64, 16), 512, DSMEM2>>>(zbf, ebf, en, cdp, cjp);
    // 5: candidates + exact rescore (+ per-row loss)
    k_cand<<<1024, 256>>>(cdp, cjp, zf, emb, en, rn, idx, out, lossr);
    // 6: out = unpatchify(emb[idx] @ W_pu + b_pu)   (unpatchify fused in store)
    k_gemm<false, true, true><<<dim3(64, 8), 256>>>(emb, wput, b_pu, out, idx,
                                                    EDIM, PIN, EDIM / 16);
    // 7: loss reduce
    k_fin2<<<1, 256>>>(lossr, out);
    (void)in_sizes; (void)n_in; (void)out_size;
}